// round 5
// baseline (speedup 1.0000x reference)
#include <cuda_runtime.h>
#include <cuda_fp16.h>
#include <cstdint>

// ---------------- problem dims ----------------
#define DIM_M 8192
#define DIM_N 16384
#define DIM_K 4096

#define BM 256
#define BN 128
#define BK 128
#define KT (DIM_K / BK)      // 32
#define MT2 (DIM_M / BM)     // 32
#define NT2 (DIM_N / BN)     // 128
#define NTILES (MT2 * NT2)   // 4096
#define GM 8                 // supertile: m-tiles per group

#define STAGE_BYTES ((BM * BK + BN * BK) * 2)   // 64K + 32K = 98304
#define SMEM_TOTAL (2 * STAGE_BYTES)            // 196608

// ---------------- device scratch (no allocs allowed) ----------------
__device__ __align__(1024) __half g_x_h[(size_t)DIM_M * DIM_K];   // 64 MB
__device__ __align__(1024) __half g_w_h[(size_t)DIM_N * DIM_K];   // 128 MB

// ---------------- PTX helpers (plain-compute_103-safe) ----------------
__device__ __forceinline__ uint32_t smem_u32(const void* p) {
    uint32_t a;
    asm("{ .reg .u64 t; cvta.to.shared.u64 t, %1; cvt.u32.u64 %0, t; }" : "=r"(a) : "l"(p));
    return a;
}

__device__ __forceinline__ void cp_async16(uint32_t saddr, const void* gaddr) {
    asm volatile("cp.async.cg.shared.global [%0], [%1], 16;" :: "r"(saddr), "l"(gaddr) : "memory");
}
#define CP_COMMIT()   asm volatile("cp.async.commit_group;" ::: "memory")
#define CP_WAIT_ALL() asm volatile("cp.async.wait_group 0;" ::: "memory")

#define LDMATRIX_X4(r0, r1, r2, r3, addr)                                              \
    asm volatile("ldmatrix.sync.aligned.m8n8.x4.shared.b16 {%0,%1,%2,%3}, [%4];"        \
                 : "=r"(r0), "=r"(r1), "=r"(r2), "=r"(r3) : "r"(addr))

#define MMA_16816(c, a, b)                                                             \
    asm volatile("mma.sync.aligned.m16n8k16.row.col.f32.f16.f16.f32 "                  \
                 "{%0,%1,%2,%3}, {%4,%5,%6,%7}, {%8,%9}, {%0,%1,%2,%3};"               \
                 : "+f"((c)[0]), "+f"((c)[1]), "+f"((c)[2]), "+f"((c)[3])              \
                 : "r"((a)[0]), "r"((a)[1]), "r"((a)[2]), "r"((a)[3]),                 \
                   "r"((b)[0]), "r"((b)[1]))

// ---------------- conversion kernels ----------------
__global__ void conv_x_f16(const float* __restrict__ x, const float* __restrict__ scale,
                           __half* __restrict__ xh, int n4) {
    int i = blockIdx.x * blockDim.x + threadIdx.x;
    if (i >= n4) return;
    float s = scale[0];
    float4 v = reinterpret_cast<const float4*>(x)[i];
    union { __half h[4]; uint2 u; } H;
    H.h[0] = __float2half(v.x * s);
    H.h[1] = __float2half(v.y * s);
    H.h[2] = __float2half(v.z * s);
    H.h[3] = __float2half(v.w * s);
    reinterpret_cast<uint2*>(xh)[i] = H.u;
}

__global__ void conv_w_f16(const float* __restrict__ w, __half* __restrict__ wh, int n4) {
    int i = blockIdx.x * blockDim.x + threadIdx.x;
    if (i >= n4) return;
    float4 v = reinterpret_cast<const float4*>(w)[i];
    union { __half h[4]; uint2 u; } H;
    H.h[0] = __float2half(v.x);
    H.h[1] = __float2half(v.y);
    H.h[2] = __float2half(v.z);
    H.h[3] = __float2half(v.w);
    reinterpret_cast<uint2*>(wh)[i] = H.u;
}

// ---------------- persistent GEMM kernel (HMMA fp16 -> fp32, 64x64 warp tiles) ----------------
// smem row = 128 fp16 = 256B = 16 chunks of 16B; physical chunk = c ^ (row & 7)
__global__ void __launch_bounds__(256, 1) hmma_gemm(
    const __half* __restrict__ Ah,   // [M, K] fp16, pre-scaled
    const __half* __restrict__ Bh,   // [N, K] fp16 (W)
    const float* __restrict__ bias,  // [N]
    float* __restrict__ out)         // [M, N]
{
    extern __shared__ char smem[];
    const uint32_t sb = smem_u32(smem);
    const int tid = threadIdx.x;
    const int wid = tid >> 5;
    const int lane = tid & 31;
    const int warp_m = wid & 3;   // 0..3 -> 64-row slabs
    const int warp_n = wid >> 2;  // 0..1 -> 64-col slabs

    // supertile raster: GM m-tiles fastest, then n, then group
    auto tile_coords = [](int t, int& m0, int& n0) {
        int mt = (t / (GM * NT2)) * GM + (t % GM);
        int nt = (t / GM) % NT2;
        m0 = mt * BM;
        n0 = nt * BN;
    };

    // one slice = 1/4 of a stage's loads (6 cp.async/thread)
    auto load_slice = [&](int s, int m0, int n0, int kt, int sl) {
        const uint32_t sA = sb + s * STAGE_BYTES;
        const uint32_t sB = sA + BM * BK * 2;
        const __half* gA = Ah + (size_t)m0 * DIM_K + (size_t)kt * BK;
        const __half* gB = Bh + (size_t)n0 * DIM_K + (size_t)kt * BK;
#pragma unroll
        for (int i = 0; i < 4; i++) {                 // A: slice of 1024 chunks
            int ch = sl * 1024 + i * 256 + tid;
            int row = ch >> 4, c = ch & 15;
            cp_async16(sA + row * 256 + ((c ^ (row & 7)) << 4),
                       gA + (size_t)row * DIM_K + c * 8);
        }
#pragma unroll
        for (int i = 0; i < 2; i++) {                 // B: slice of 512 chunks
            int ch = sl * 512 + i * 256 + tid;
            int row = ch >> 4, c = ch & 15;
            cp_async16(sB + row * 256 + ((c ^ (row & 7)) << 4),
                       gB + (size_t)row * DIM_K + c * 8);
        }
    };

    int t = blockIdx.x;
    if (t >= NTILES) return;
    int m0, n0;
    tile_coords(t, m0, n0);

    // prologue: tile t chunk 0 -> stage 0
#pragma unroll
    for (int sl = 0; sl < 4; sl++) load_slice(0, m0, n0, 0, sl);
    CP_COMMIT();

    unsigned cnt = 0;   // global chunk counter -> stage parity across tiles
    float acc[4][8][4];

    while (true) {
        const int tn = t + gridDim.x;
        const bool has_next = (tn < NTILES);
        int m0n = 0, n0n = 0;
        if (has_next) tile_coords(tn, m0n, n0n);

#pragma unroll
        for (int i = 0; i < 4; i++)
#pragma unroll
            for (int j = 0; j < 8; j++)
#pragma unroll
                for (int q = 0; q < 4; q++) acc[i][j][q] = 0.0f;

        for (int kt = 0; kt < KT; kt++, cnt++) {
            const int stage = cnt & 1;
            CP_WAIT_ALL();        // chunk cnt complete (committed a full chunk ago)
            __syncthreads();      // publish stage; all reads of other stage done

            const uint32_t sA = sb + stage * STAGE_BYTES;
            const uint32_t sB = sA + BM * BK * 2;
            const bool last_k = (kt + 1 == KT);

#pragma unroll
            for (int ks = 0; ks < 8; ks++) {   // 8 x k16 per BK=128 chunk
                // A fragments: 4 m16 tiles (64 rows)
                uint32_t a[4][4];
#pragma unroll
                for (int mi = 0; mi < 4; mi++) {
                    int row = warp_m * 64 + mi * 16 + (lane & 15);
                    int chunk = ks * 2 + (lane >> 4);
                    uint32_t addr = sA + row * 256 + ((chunk ^ (row & 7)) << 4);
                    LDMATRIX_X4(a[mi][0], a[mi][1], a[mi][2], a[mi][3], addr);
                }
                // B fragments: 8 n8 tiles (64 cols), 2 per ldmatrix.x4
                uint32_t b[8][2];
#pragma unroll
                for (int p = 0; p < 4; p++) {
                    int lane8 = lane & 7;
                    int g = lane >> 3;
                    int rowb = warp_n * 64 + p * 16 + ((g & 2) ? 8 : 0) + lane8;
                    int chunk = ks * 2 + (g & 1);
                    uint32_t addr = sB + rowb * 256 + ((chunk ^ (rowb & 7)) << 4);
                    LDMATRIX_X4(b[2 * p][0], b[2 * p][1], b[2 * p + 1][0], b[2 * p + 1][1], addr);
                }
#pragma unroll
                for (int mi = 0; mi < 4; mi++)
#pragma unroll
                    for (int ni = 0; ni < 8; ni++)
                        MMA_16816(acc[mi][ni], a[mi], b[ni]);

                // spread next-chunk loads across the first 4 sub-iterations;
                // on the last k-chunk, prefetch NEXT TILE's chunk 0 instead
                if (ks < 4) {
                    if (!last_k)        load_slice(stage ^ 1, m0, n0, kt + 1, ks);
                    else if (has_next)  load_slice(stage ^ 1, m0n, n0n, 0, ks);
                }
            }
            CP_COMMIT();          // one group per chunk
        }

        // -------- epilogue (next tile's chunk 0 already in flight) --------
        {
            float2 bv[8];
#pragma unroll
            for (int ni = 0; ni < 8; ni++) {
                int col = n0 + warp_n * 64 + ni * 8 + 2 * (lane & 3);
                bv[ni] = *reinterpret_cast<const float2*>(bias + col);
            }
#pragma unroll
            for (int mi = 0; mi < 4; mi++) {
                size_t r0 = (size_t)(m0 + warp_m * 64 + mi * 16 + (lane >> 2));
                size_t r1 = r0 + 8;
#pragma unroll
                for (int ni = 0; ni < 8; ni++) {
                    int col = n0 + warp_n * 64 + ni * 8 + 2 * (lane & 3);
                    float2 v0 = make_float2(acc[mi][ni][0] + bv[ni].x, acc[mi][ni][1] + bv[ni].y);
                    float2 v1 = make_float2(acc[mi][ni][2] + bv[ni].x, acc[mi][ni][3] + bv[ni].y);
                    *reinterpret_cast<float2*>(out + r0 * DIM_N + col) = v0;
                    *reinterpret_cast<float2*>(out + r1 * DIM_N + col) = v1;
                }
            }
        }

        if (!has_next) break;
        t = tn; m0 = m0n; n0 = n0n;
    }
}

// ---------------- host launch ----------------
extern "C" void kernel_launch(void* const* d_in, const int* in_sizes, int n_in,
                              void* d_out, int out_size) {
    const float* x     = (const float*)d_in[0];
    const float* w     = (const float*)d_in[1];
    const float* scale = (const float*)d_in[2];
    const float* bias  = (const float*)d_in[3];
    float* out = (float*)d_out;

    void *p_xh = nullptr, *p_wh = nullptr;
    cudaGetSymbolAddress(&p_xh, g_x_h);
    cudaGetSymbolAddress(&p_wh, g_w_h);

    const int n4x = DIM_M * DIM_K / 4;
    conv_x_f16<<<n4x / 256, 256>>>(x, scale, (__half*)p_xh, n4x);
    const int n4w = (int)((size_t)DIM_N * DIM_K / 4);
    conv_w_f16<<<n4w / 256, 256>>>(w, (__half*)p_wh, n4w);

    int nsm = 148;
    cudaDeviceGetAttribute(&nsm, cudaDevAttrMultiProcessorCount, 0);
    if (nsm <= 0 || nsm > NTILES) nsm = 148;

    cudaFuncSetAttribute(hmma_gemm, cudaFuncAttributeMaxDynamicSharedMemorySize, SMEM_TOTAL);
    hmma_gemm<<<nsm, 256, SMEM_TOTAL>>>((const __half*)p_xh, (const __half*)p_wh, bias, out);
}

// round 6
// speedup vs baseline: 1.1023x; 1.1023x over previous
#include <cuda_runtime.h>
#include <cuda_fp16.h>
#include <cstdint>

// ---------------- problem dims ----------------
#define DIM_M 8192
#define DIM_N 16384
#define DIM_K 4096

#define BM 256
#define BN 128
#define BK 128
#define STAGES 2
#define KT (DIM_K / BK)      // 32
#define MT2 (DIM_M / BM)     // 32
#define NT2 (DIM_N / BN)     // 128
#define GM 16                // supertile: m-tiles per group (2 groups -> B swept 2x)

#define STAGE_BYTES ((BM * BK + BN * BK) * 2)   // 64K + 32K = 98304
#define SMEM_TOTAL (STAGES * STAGE_BYTES)       // 196608

// ---------------- device scratch (no allocs allowed) ----------------
__device__ __align__(1024) __half g_x_h[(size_t)DIM_M * DIM_K];   // 64 MB
__device__ __align__(1024) __half g_w_h[(size_t)DIM_N * DIM_K];   // 128 MB

// ---------------- PTX helpers (plain-compute_103-safe) ----------------
__device__ __forceinline__ uint32_t smem_u32(const void* p) {
    uint32_t a;
    asm("{ .reg .u64 t; cvta.to.shared.u64 t, %1; cvt.u32.u64 %0, t; }" : "=r"(a) : "l"(p));
    return a;
}

__device__ __forceinline__ void cp_async16(uint32_t saddr, const void* gaddr) {
    asm volatile("cp.async.cg.shared.global [%0], [%1], 16;" :: "r"(saddr), "l"(gaddr) : "memory");
}
#define CP_COMMIT()   asm volatile("cp.async.commit_group;" ::: "memory")
#define CP_WAIT_ALL() asm volatile("cp.async.wait_group 0;" ::: "memory")

#define LDMATRIX_X4(r0, r1, r2, r3, addr)                                              \
    asm volatile("ldmatrix.sync.aligned.m8n8.x4.shared.b16 {%0,%1,%2,%3}, [%4];"        \
                 : "=r"(r0), "=r"(r1), "=r"(r2), "=r"(r3) : "r"(addr))

#define MMA_16816(c, a, b)                                                             \
    asm volatile("mma.sync.aligned.m16n8k16.row.col.f32.f16.f16.f32 "                  \
                 "{%0,%1,%2,%3}, {%4,%5,%6,%7}, {%8,%9}, {%0,%1,%2,%3};"               \
                 : "+f"((c)[0]), "+f"((c)[1]), "+f"((c)[2]), "+f"((c)[3])              \
                 : "r"((a)[0]), "r"((a)[1]), "r"((a)[2]), "r"((a)[3]),                 \
                   "r"((b)[0]), "r"((b)[1]))

// ---------------- conversion kernels (8 elements / thread) ----------------
__global__ void conv_x_f16(const float* __restrict__ x, const float* __restrict__ scale,
                           __half* __restrict__ xh, int n8) {
    int i = blockIdx.x * blockDim.x + threadIdx.x;
    if (i >= n8) return;
    float s = scale[0];
    float4 v0 = reinterpret_cast<const float4*>(x)[2 * i];
    float4 v1 = reinterpret_cast<const float4*>(x)[2 * i + 1];
    union { __half h[8]; uint4 u; } H;
    H.h[0] = __float2half(v0.x * s); H.h[1] = __float2half(v0.y * s);
    H.h[2] = __float2half(v0.z * s); H.h[3] = __float2half(v0.w * s);
    H.h[4] = __float2half(v1.x * s); H.h[5] = __float2half(v1.y * s);
    H.h[6] = __float2half(v1.z * s); H.h[7] = __float2half(v1.w * s);
    reinterpret_cast<uint4*>(xh)[i] = H.u;
}

__global__ void conv_w_f16(const float* __restrict__ w, __half* __restrict__ wh, int n8) {
    int i = blockIdx.x * blockDim.x + threadIdx.x;
    if (i >= n8) return;
    float4 v0 = reinterpret_cast<const float4*>(w)[2 * i];
    float4 v1 = reinterpret_cast<const float4*>(w)[2 * i + 1];
    union { __half h[8]; uint4 u; } H;
    H.h[0] = __float2half(v0.x); H.h[1] = __float2half(v0.y);
    H.h[2] = __float2half(v0.z); H.h[3] = __float2half(v0.w);
    H.h[4] = __float2half(v1.x); H.h[5] = __float2half(v1.y);
    H.h[6] = __float2half(v1.z); H.h[7] = __float2half(v1.w);
    reinterpret_cast<uint4*>(wh)[i] = H.u;
}

// ---------------- main GEMM kernel (HMMA fp16 -> fp32, 64x64 warp tiles) ----------------
// smem row = 128 fp16 = 256B = 16 chunks of 16B; physical chunk = c ^ (row & 7)
__global__ void __launch_bounds__(256, 1) hmma_gemm(
    const __half* __restrict__ Ah,   // [M, K] fp16, pre-scaled
    const __half* __restrict__ Bh,   // [N, K] fp16 (W)
    const float* __restrict__ bias,  // [N]
    float* __restrict__ out)         // [M, N]
{
    extern __shared__ char smem[];
    const uint32_t sb = smem_u32(smem);
    const int tid = threadIdx.x;
    const int wid = tid >> 5;
    const int lane = tid & 31;
    const int warp_m = wid & 3;   // 0..3 -> 64-row slabs
    const int warp_n = wid >> 2;  // 0..1 -> 64-col slabs

    // supertile raster: GM m-tiles fastest, then n, then group
    const int bid = blockIdx.x;
    const int mt = (bid / (GM * NT2)) * GM + (bid % GM);
    const int nt = (bid / GM) % NT2;
    const int m0 = mt * BM;
    const int n0 = nt * BN;

    // one slice = 1/4 of a stage's loads: A 1024 chunks + B 512 chunks => 6 cp.async/thread
    auto load_slice = [&](int s, int kt, int sl) {
        const uint32_t sA = sb + s * STAGE_BYTES;
        const uint32_t sB = sA + BM * BK * 2;
        const __half* gA = Ah + (size_t)m0 * DIM_K + (size_t)kt * BK;
        const __half* gB = Bh + (size_t)n0 * DIM_K + (size_t)kt * BK;
#pragma unroll
        for (int i = 0; i < 4; i++) {                 // A: slice of 1024 chunks
            int ch = sl * 1024 + i * 256 + tid;
            int row = ch >> 4, c = ch & 15;
            cp_async16(sA + row * 256 + ((c ^ (row & 7)) << 4),
                       gA + (size_t)row * DIM_K + c * 8);
        }
#pragma unroll
        for (int i = 0; i < 2; i++) {                 // B: slice of 512 chunks
            int ch = sl * 512 + i * 256 + tid;
            int row = ch >> 4, c = ch & 15;
            cp_async16(sB + row * 256 + ((c ^ (row & 7)) << 4),
                       gB + (size_t)row * DIM_K + c * 8);
        }
    };

    float acc[4][8][4];
#pragma unroll
    for (int i = 0; i < 4; i++)
#pragma unroll
        for (int j = 0; j < 8; j++)
#pragma unroll
            for (int q = 0; q < 4; q++) acc[i][j][q] = 0.0f;

    // prologue: stage 0 fully in flight
#pragma unroll
    for (int sl = 0; sl < 4; sl++) load_slice(0, 0, sl);
    CP_COMMIT();

    for (int kt = 0; kt < KT; kt++) {
        const int stage = kt & 1;
        CP_WAIT_ALL();        // group kt complete
        __syncthreads();      // publish stage kt; all reads of stage kt-1 done

        const uint32_t sA = sb + stage * STAGE_BYTES;
        const uint32_t sB = sA + BM * BK * 2;
        const bool more = (kt + 1 < KT);

#pragma unroll
        for (int ks = 0; ks < 8; ks++) {   // 8 x k16 per BK=128 chunk
            // A fragments: 4 m16 tiles (64 rows)
            uint32_t a[4][4];
#pragma unroll
            for (int mi = 0; mi < 4; mi++) {
                int row = warp_m * 64 + mi * 16 + (lane & 15);
                int chunk = ks * 2 + (lane >> 4);
                uint32_t addr = sA + row * 256 + ((chunk ^ (row & 7)) << 4);
                LDMATRIX_X4(a[mi][0], a[mi][1], a[mi][2], a[mi][3], addr);
            }
            // B fragments: 8 n8 tiles (64 cols), 2 per ldmatrix.x4
            uint32_t b[8][2];
#pragma unroll
            for (int p = 0; p < 4; p++) {
                int lane8 = lane & 7;
                int g = lane >> 3;
                int rowb = warp_n * 64 + p * 16 + ((g & 2) ? 8 : 0) + lane8;
                int chunk = ks * 2 + (g & 1);
                uint32_t addr = sB + rowb * 256 + ((chunk ^ (rowb & 7)) << 4);
                LDMATRIX_X4(b[2 * p][0], b[2 * p][1], b[2 * p + 1][0], b[2 * p + 1][1], addr);
            }
#pragma unroll
            for (int mi = 0; mi < 4; mi++)
#pragma unroll
                for (int ni = 0; ni < 8; ni++)
                    MMA_16816(acc[mi][ni], a[mi], b[ni]);

            // spread next-chunk loads across the first 4 sub-iterations
            if (ks < 4 && more) load_slice(stage ^ 1, kt + 1, ks);
        }
        CP_COMMIT();          // one group per chunk
    }

    // -------- epilogue: direct register -> gmem (float2), + bias --------
    float2 bv[8];
#pragma unroll
    for (int ni = 0; ni < 8; ni++) {
        int col = n0 + warp_n * 64 + ni * 8 + 2 * (lane & 3);
        bv[ni] = *reinterpret_cast<const float2*>(bias + col);
    }
#pragma unroll
    for (int mi = 0; mi < 4; mi++) {
        size_t r0 = (size_t)(m0 + warp_m * 64 + mi * 16 + (lane >> 2));
        size_t r1 = r0 + 8;
#pragma unroll
        for (int ni = 0; ni < 8; ni++) {
            int col = n0 + warp_n * 64 + ni * 8 + 2 * (lane & 3);
            float2 v0 = make_float2(acc[mi][ni][0] + bv[ni].x, acc[mi][ni][1] + bv[ni].y);
            float2 v1 = make_float2(acc[mi][ni][2] + bv[ni].x, acc[mi][ni][3] + bv[ni].y);
            *reinterpret_cast<float2*>(out + r0 * DIM_N + col) = v0;
            *reinterpret_cast<float2*>(out + r1 * DIM_N + col) = v1;
        }
    }
}

// ---------------- host launch ----------------
extern "C" void kernel_launch(void* const* d_in, const int* in_sizes, int n_in,
                              void* d_out, int out_size) {
    const float* x     = (const float*)d_in[0];
    const float* w     = (const float*)d_in[1];
    const float* scale = (const float*)d_in[2];
    const float* bias  = (const float*)d_in[3];
    float* out = (float*)d_out;

    void *p_xh = nullptr, *p_wh = nullptr;
    cudaGetSymbolAddress(&p_xh, g_x_h);
    cudaGetSymbolAddress(&p_wh, g_w_h);

    const int n8x = DIM_M * DIM_K / 8;
    conv_x_f16<<<n8x / 256, 256>>>(x, scale, (__half*)p_xh, n8x);
    const int n8w = (int)((size_t)DIM_N * DIM_K / 8);
    conv_w_f16<<<n8w / 256, 256>>>(w, (__half*)p_wh, n8w);

    cudaFuncSetAttribute(hmma_gemm, cudaFuncAttributeMaxDynamicSharedMemorySize, SMEM_TOTAL);
    hmma_gemm<<<MT2 * NT2, 256, SMEM_TOTAL>>>((const __half*)p_xh, (const __half*)p_wh, bias, out);
}